// round 6
// baseline (speedup 1.0000x reference)
#include <cuda_runtime.h>
#include <math.h>

#define H 1024
#define V 50257
#define L 40

// ---- scratch (__device__ globals: allocation-free) ----
__device__ float g_xa[2 * H];     // [x ; attn_applied]
__device__ float g_g[H];          // relu(comb)
__device__ float g_gi[3 * H];
__device__ float g_gh[3 * H];
__device__ float g_hnew[H];
__device__ float g_pm[1184];      // per-block partial max
__device__ float g_ps[1184];      // per-block partial sumexp
__device__ float g_logZ;

__device__ __forceinline__ float warp_sum(float v) {
    #pragma unroll
    for (int o = 16; o; o >>= 1) v += __shfl_xor_sync(0xffffffffu, v, o);
    return v;
}

// ---------------------------------------------------------------------------
// Kernel A: embedding gather, attention logits, softmax, attn_applied.
// 1 block, 1024 threads. Writes attn_w to out[V+H ..), fills g_xa.
// ---------------------------------------------------------------------------
__global__ __launch_bounds__(1024, 1)
void k_attn(const int* __restrict__ input,
            const float* __restrict__ hidden,
            const float* __restrict__ enc,
            const float* __restrict__ emb,
            const float* __restrict__ W_attn,
            const float* __restrict__ b_attn,
            float* __restrict__ out) {
    __shared__ float sh_xh[2 * H];
    __shared__ float sh_logit[L];
    __shared__ float sh_w[L];
    const int tid = threadIdx.x;          // 0..1023
    const int row_idx = input[0];

    float xv = emb[(size_t)row_idx * H + tid];
    sh_xh[tid] = xv;
    sh_xh[H + tid] = hidden[tid];
    g_xa[tid] = xv;
    __syncthreads();

    const int warp = tid >> 5, lane = tid & 31;
    const float4* xh4 = (const float4*)sh_xh;
    for (int r = warp; r < L; r += 32) {
        const float4* wr = (const float4*)(W_attn + (size_t)r * 2 * H);
        float acc = 0.f;
        for (int k = lane; k < 2 * H / 4; k += 32) {
            float4 a = wr[k], b = xh4[k];
            acc += a.x * b.x + a.y * b.y + a.z * b.z + a.w * b.w;
        }
        acc = warp_sum(acc);
        if (lane == 0) sh_logit[r] = acc + b_attn[r];
    }
    __syncthreads();

    if (tid == 0) {  // 40 elements: serial softmax is negligible
        float m = sh_logit[0];
        for (int l = 1; l < L; l++) m = fmaxf(m, sh_logit[l]);
        float s = 0.f;
        for (int l = 0; l < L; l++) { float e = __expf(sh_logit[l] - m); sh_w[l] = e; s += e; }
        float inv = 1.f / s;
        for (int l = 0; l < L; l++) sh_w[l] *= inv;
    }
    __syncthreads();

    if (tid < L) out[V + H + tid] = sh_w[tid];

    // attn_applied[j] = sum_l w[l] * enc[l][j]   (coalesced over j)
    float acc = 0.f;
    #pragma unroll 8
    for (int l = 0; l < L; l++) acc += sh_w[l] * enc[l * H + tid];
    g_xa[H + tid] = acc;
}

// ---------------------------------------------------------------------------
// Kernel B: g = relu(W_comb @ [x; attn_applied] + b_comb). 128 blocks x 256,
// warp-per-row (8 rows/block), operand staged in SMEM.
// ---------------------------------------------------------------------------
__global__ __launch_bounds__(256, 8)
void k_comb(const float* __restrict__ W_comb,
            const float* __restrict__ b_comb) {
    __shared__ float4 sh[2 * H / 4];
    const int tid = threadIdx.x;
    for (int k = tid; k < 2 * H / 4; k += 256) sh[k] = ((const float4*)g_xa)[k];
    __syncthreads();
    const int warp = tid >> 5, lane = tid & 31;
    const int row = blockIdx.x * 8 + warp;   // exactly 1024 rows
    const float4* wr = (const float4*)(W_comb + (size_t)row * 2 * H);
    float acc = 0.f;
    #pragma unroll 4
    for (int k = lane; k < 2 * H / 4; k += 32) {
        float4 a = wr[k], b = sh[k];
        acc += a.x * b.x + a.y * b.y + a.z * b.z + a.w * b.w;
    }
    acc = warp_sum(acc);
    if (lane == 0) g_g[row] = fmaxf(acc + b_comb[row], 0.f);
}

// ---------------------------------------------------------------------------
// Kernel C: gi = W_ih @ g + b_ih ; gh = W_hh @ h + b_hh. 384 blocks x 256,
// warp computes BOTH dots for its row (8 KB weight read per warp).
// ---------------------------------------------------------------------------
__global__ __launch_bounds__(256, 8)
void k_gru_mm(const float* __restrict__ W_ih,
              const float* __restrict__ b_ih,
              const float* __restrict__ W_hh,
              const float* __restrict__ b_hh,
              const float* __restrict__ hidden) {
    __shared__ float4 shg[H / 4];
    __shared__ float4 shh[H / 4];
    const int tid = threadIdx.x;
    for (int k = tid; k < H / 4; k += 256) {
        shg[k] = ((const float4*)g_g)[k];
        shh[k] = ((const float4*)hidden)[k];
    }
    __syncthreads();
    const int warp = tid >> 5, lane = tid & 31;
    const int row = blockIdx.x * 8 + warp;   // exactly 3072 rows
    const float4* wi = (const float4*)(W_ih + (size_t)row * H);
    const float4* wh = (const float4*)(W_hh + (size_t)row * H);
    float ai = 0.f, ah = 0.f;
    #pragma unroll 4
    for (int k = lane; k < H / 4; k += 32) {
        float4 a = wi[k], b = shg[k];
        ai += a.x * b.x + a.y * b.y + a.z * b.z + a.w * b.w;
        float4 c = wh[k], d = shh[k];
        ah += c.x * d.x + c.y * d.y + c.z * d.z + c.w * d.w;
    }
    ai = warp_sum(ai);
    ah = warp_sum(ah);
    if (lane == 0) {
        g_gi[row] = ai + b_ih[row];
        g_gh[row] = ah + b_hh[row];
    }
}

// ---------------------------------------------------------------------------
// Kernel D: GRU gate elementwise -> h_new; writes out[V .. V+H).
// Exactly H threads (4 blocks x 256).
// ---------------------------------------------------------------------------
__global__ __launch_bounds__(256)
void k_gate(const float* __restrict__ hidden, float* __restrict__ out) {
    const int i = blockIdx.x * blockDim.x + threadIdx.x;   // 0..1023
    float r = 1.f / (1.f + expf(-(g_gi[i] + g_gh[i])));
    float z = 1.f / (1.f + expf(-(g_gi[H + i] + g_gh[H + i])));
    float n = tanhf(g_gi[2 * H + i] + r * g_gh[2 * H + i]);
    float hn = (1.f - z) * n + z * hidden[i];
    g_hnew[i] = hn;
    out[V + i] = hn;
}

// ---------------------------------------------------------------------------
// Kernel E (dominant, ~206 MB): logits = W_out @ h_new + b_out, stored to
// out[0..V), fused per-block online (max, sumexp) partials.
// 1184 blocks (= 8 * 148 SMs) x 256 threads; each warp computes TWO rows
// per iteration (16 LDG.128 in flight per lane, shfl cost amortized).
// ---------------------------------------------------------------------------
#define LOGIT_BLOCKS 1184
__global__ __launch_bounds__(256, 8)
void k_logits(const float* __restrict__ W_out,
              const float* __restrict__ b_out,
              float* __restrict__ out) {
    __shared__ float4 shh[H / 4];
    __shared__ float sm[8], ss[8];
    const int tid = threadIdx.x;
    for (int k = tid; k < H / 4; k += 256) shh[k] = ((const float4*)g_hnew)[k];
    __syncthreads();
    const int warp = tid >> 5, lane = tid & 31;
    float m = -1e30f, s = 0.f;
    // 16 rows per block per iteration; warp handles rows (base+warp*2, +1)
    for (int base = blockIdx.x * 16; base < V; base += LOGIT_BLOCKS * 16) {
        const int row0 = base + warp * 2;
        const int row1 = row0 + 1;
        float acc0 = 0.f, acc1 = 0.f;
        if (row0 < V) {
            const float4* wr0 = (const float4*)(W_out + (size_t)row0 * H);
            if (row1 < V) {
                const float4* wr1 = (const float4*)(W_out + (size_t)row1 * H);
                #pragma unroll 8
                for (int k = lane; k < H / 4; k += 32) {
                    float4 b = shh[k];
                    float4 a0 = wr0[k];
                    float4 a1 = wr1[k];
                    acc0 += a0.x * b.x + a0.y * b.y + a0.z * b.z + a0.w * b.w;
                    acc1 += a1.x * b.x + a1.y * b.y + a1.z * b.z + a1.w * b.w;
                }
            } else {
                #pragma unroll 8
                for (int k = lane; k < H / 4; k += 32) {
                    float4 b = shh[k];
                    float4 a0 = wr0[k];
                    acc0 += a0.x * b.x + a0.y * b.y + a0.z * b.z + a0.w * b.w;
                }
            }
        }
        acc0 = warp_sum(acc0);
        acc1 = warp_sum(acc1);
        if (lane == 0 && row0 < V) {
            float l0 = acc0 + b_out[row0];
            out[row0] = l0;
            float mn = fmaxf(m, l0);
            s = s * __expf(m - mn) + __expf(l0 - mn);
            m = mn;
            if (row1 < V) {
                float l1 = acc1 + b_out[row1];
                out[row1] = l1;
                mn = fmaxf(m, l1);
                s = s * __expf(m - mn) + __expf(l1 - mn);
                m = mn;
            }
        }
    }
    if (lane == 0) { sm[warp] = m; ss[warp] = s; }
    __syncthreads();
    if (tid == 0) {
        float M = sm[0], S = ss[0];
        #pragma unroll
        for (int w = 1; w < 8; w++) {
            float mn = fmaxf(M, sm[w]);
            S = S * __expf(M - mn) + ss[w] * __expf(sm[w] - mn);
            M = mn;
        }
        g_pm[blockIdx.x] = M;
        g_ps[blockIdx.x] = S;
    }
}

// ---------------------------------------------------------------------------
// Kernel F: reduce 1184 (m,s) partials -> logZ. 1 block, 1024 threads.
// ---------------------------------------------------------------------------
__global__ __launch_bounds__(1024, 1)
void k_reduceZ() {
    __shared__ float sm[32], ss[32];
    const int tid = threadIdx.x;
    float m = -1e30f, s = 0.f;
    for (int i = tid; i < LOGIT_BLOCKS; i += 1024) {
        float m2 = g_pm[i], s2 = g_ps[i];
        float mn = fmaxf(m, m2);
        s = s * __expf(m - mn) + s2 * __expf(m2 - mn);
        m = mn;
    }
    #pragma unroll
    for (int o = 16; o; o >>= 1) {
        float m2 = __shfl_xor_sync(0xffffffffu, m, o);
        float s2 = __shfl_xor_sync(0xffffffffu, s, o);
        float mn = fmaxf(m, m2);
        s = s * __expf(m - mn) + s2 * __expf(m2 - mn);
        m = mn;
    }
    if ((tid & 31) == 0) { sm[tid >> 5] = m; ss[tid >> 5] = s; }
    __syncthreads();
    if (tid < 32) {
        m = sm[tid]; s = ss[tid];
        #pragma unroll
        for (int o = 16; o; o >>= 1) {
            float m2 = __shfl_xor_sync(0xffffffffu, m, o);
            float s2 = __shfl_xor_sync(0xffffffffu, s, o);
            float mn = fmaxf(m, m2);
            s = s * __expf(m - mn) + s2 * __expf(m2 - mn);
            m = mn;
        }
        if (tid == 0) g_logZ = m + logf(s);
    }
}

// ---------------------------------------------------------------------------
// Kernel G: out[v] -= logZ, float4-vectorized (V = 50257 = 12564*4 + 1).
// ---------------------------------------------------------------------------
__global__ __launch_bounds__(256)
void k_finish(float* __restrict__ out) {
    const float lz = g_logZ;
    const int n4 = V / 4;                 // 12564 float4s
    float4* o4 = (float4*)out;
    for (int i = blockIdx.x * blockDim.x + threadIdx.x; i < n4;
         i += gridDim.x * blockDim.x) {
        float4 v = o4[i];
        v.x -= lz; v.y -= lz; v.z -= lz; v.w -= lz;
        o4[i] = v;
    }
    if (blockIdx.x == 0 && threadIdx.x == 0) out[V - 1] -= lz;  // remainder
}

// ---------------------------------------------------------------------------
extern "C" void kernel_launch(void* const* d_in, const int* in_sizes, int n_in,
                              void* d_out, int out_size) {
    const int*   input  = (const int*)  d_in[0];
    const float* hidden = (const float*)d_in[1];
    const float* enc    = (const float*)d_in[2];
    const float* emb    = (const float*)d_in[3];
    const float* W_attn = (const float*)d_in[4];
    const float* b_attn = (const float*)d_in[5];
    const float* W_comb = (const float*)d_in[6];
    const float* b_comb = (const float*)d_in[7];
    const float* W_ih   = (const float*)d_in[8];
    const float* b_ih   = (const float*)d_in[9];
    const float* W_hh   = (const float*)d_in[10];
    const float* b_hh   = (const float*)d_in[11];
    const float* W_out  = (const float*)d_in[12];
    const float* b_out  = (const float*)d_in[13];
    float* out = (float*)d_out;

    k_attn  <<<1, 1024>>>(input, hidden, enc, emb, W_attn, b_attn, out);
    k_comb  <<<128, 256>>>(W_comb, b_comb);
    k_gru_mm<<<384, 256>>>(W_ih, b_ih, W_hh, b_hh, hidden);
    k_gate  <<<4, 256>>>(hidden, out);
    k_logits<<<LOGIT_BLOCKS, 256>>>(W_out, b_out, out);
    k_reduceZ<<<1, 1024>>>();
    k_finish<<<100, 256>>>(out);
}